// round 4
// baseline (speedup 1.0000x reference)
#include <cuda_runtime.h>
#include <math.h>
#include <stdint.h>

#define NN 8
#define CC 1024
#define BB 2048
#define EPS 1e-12f

// ---- scratch (device globals; no allocation allowed) ----
__device__ float g_K[(size_t)NN * CC * BB];    // 64 MB (tf32-rounded fp32)
__device__ float g_Q[(size_t)NN * CC * BB];    // 64 MB (tf32-rounded fp32)
__device__ float g_Y[(size_t)NN * BB * BB];    // 128 MB
__device__ float g_Xt[(size_t)NN * CC * BB];   // 64 MB (X tf32-rounded)
__device__ float g_Wkt[CC * CC];
__device__ float g_Wqt[CC * CC];
__device__ float g_DK2[NN * BB];
__device__ float g_DQ2[NN * BB];

__device__ __forceinline__ uint32_t f2tf(float f) {
    uint32_t r;
    asm volatile("cvt.rna.tf32.f32 %0, %1;" : "=r"(r) : "f"(f));
    return r;
}
__device__ __forceinline__ float roundtf(float f) { return __uint_as_float(f2tf(f)); }

__device__ __forceinline__ void cp16(float* smem, const float* g) {
    uint32_t s = (uint32_t)__cvta_generic_to_shared(smem);
    asm volatile("cp.async.cg.shared.global [%0], [%1], 16;" :: "r"(s), "l"(g));
}
__device__ __forceinline__ void cp_commit() {
    asm volatile("cp.async.commit_group;");
}

__device__ __forceinline__ void mma_tf32(float (&d)[4], const uint32_t (&a)[4],
                                         const uint32_t (&b)[2]) {
    asm volatile(
        "mma.sync.aligned.m16n8k8.row.col.f32.tf32.tf32.f32 "
        "{%0,%1,%2,%3}, {%4,%5,%6,%7}, {%8,%9}, {%0,%1,%2,%3};"
        : "+f"(d[0]), "+f"(d[1]), "+f"(d[2]), "+f"(d[3])
        : "r"(a[0]), "r"(a[1]), "r"(a[2]), "r"(a[3]),
          "r"(b[0]), "r"(b[1]));
}

// ===========================================================================
// TF32 warp-MMA GEMM: CTA tile 128x256, 512 threads = 16 warps (4m x 4n),
// warp tile 32x64, BK=16, 2-stage cp.async pipeline.
// Operands pre-rounded to TF32 in gmem -> inner loop is pure LDS + HMMA.
// MODE: 0 = proj (C = A@B + bias, output tf32-rounded)
//       1 = score (C = A^T@B * rsqrt(dq*dk), output fp32)
//       2 = mix   (C = A@B, output fp32)
// AKM:  A tile stored k-major (A column-major in gmem: elem(m,k)=A[k*lda+m])
// ===========================================================================
#define BM 128
#define BN 256
#define BK 16
#define SB_STRIDE 264   // [16][256+8]
#define SB_SZ (16 * SB_STRIDE)

template <int MODE, int KDIM, bool AKM>
__global__ __launch_bounds__(512)
void gemm_tf32(const float* __restrict__ A, int lda, size_t strA,
               const float* __restrict__ B, int ldb, size_t strB,
               float* __restrict__ C, int ldc, size_t strC,
               const float* __restrict__ bias,
               const float* __restrict__ dq2_all,
               const float* __restrict__ dk2_all)
{
    constexpr int SA_SZ = AKM ? 16 * 136 : 128 * 20;
    constexpr int STAGE = SA_SZ + SB_SZ;
    extern __shared__ float smem[];

    const int n = blockIdx.z;
    const float* An = A + (size_t)n * strA;
    const float* Bn = B + (size_t)n * strB;
    float* Cn = C + (size_t)n * strC;

    const int row0 = blockIdx.y * BM;
    const int col0 = blockIdx.x * BN;

    const int tid = threadIdx.x;
    const int lane = tid & 31;
    const int warp = tid >> 5;
    const int wm = warp >> 2;   // 0..3 (32-row slab)
    const int wn = warp & 3;    // 0..3 (64-col slab)
    const int lr = lane >> 2;   // 0..7
    const int lc = lane & 3;    // 0..3

    float acc[2][8][4] = {};

    auto loadA = [&](float* s, int k0) {
        if (!AKM) {
            // 128x16: 512 cp16 -> 1 per thread
            int r = tid >> 2, sg = tid & 3;
            cp16(s + r * 20 + sg * 4,
                 An + (size_t)(row0 + r) * lda + k0 + sg * 4);
        } else {
            // 16x128: 512 cp16 -> 1 per thread
            int r = tid >> 5, sg = tid & 31;
            cp16(s + r * 136 + sg * 4,
                 An + (size_t)(k0 + r) * lda + row0 + sg * 4);
        }
    };
    auto loadB = [&](float* s, int k0) {
        // 16x256: 1024 cp16 -> 2 per thread
        #pragma unroll
        for (int i = tid; i < 1024; i += 512) {
            int r = i >> 6, sg = i & 63;
            cp16(s + r * SB_STRIDE + sg * 4,
                 Bn + (size_t)(k0 + r) * ldb + col0 + sg * 4);
        }
    };

    constexpr int KTILES = KDIM / BK;

    // prologue
    loadA(smem, 0);
    loadB(smem + SA_SZ, 0);
    cp_commit();

    for (int kt = 0; kt < KTILES; kt++) {
        const int buf = kt & 1;
        if (kt + 1 < KTILES) {
            float* s = smem + (buf ^ 1) * STAGE;
            loadA(s, (kt + 1) * BK);
            loadB(s + SA_SZ, (kt + 1) * BK);
            cp_commit();
            asm volatile("cp.async.wait_group 1;");
        } else {
            asm volatile("cp.async.wait_group 0;");
        }
        __syncthreads();

        const float* cA = smem + buf * STAGE;
        const float* cB = cA + SA_SZ;

        #pragma unroll
        for (int ks = 0; ks < 2; ks++) {
            const int kb = ks * 8;
            uint32_t af[2][4];
            uint32_t bf[8][2];

            #pragma unroll
            for (int mi = 0; mi < 2; mi++) {
                const int r = wm * 32 + mi * 16 + lr;
                const int c = kb + lc;
                if (!AKM) {
                    af[mi][0] = __float_as_uint(cA[r * 20 + c]);
                    af[mi][1] = __float_as_uint(cA[(r + 8) * 20 + c]);
                    af[mi][2] = __float_as_uint(cA[r * 20 + c + 4]);
                    af[mi][3] = __float_as_uint(cA[(r + 8) * 20 + c + 4]);
                } else {
                    af[mi][0] = __float_as_uint(cA[c * 136 + r]);
                    af[mi][1] = __float_as_uint(cA[c * 136 + r + 8]);
                    af[mi][2] = __float_as_uint(cA[(c + 4) * 136 + r]);
                    af[mi][3] = __float_as_uint(cA[(c + 4) * 136 + r + 8]);
                }
            }
            #pragma unroll
            for (int ni = 0; ni < 8; ni++) {
                const int kr = kb + lc;
                const int nc = wn * 64 + ni * 8 + lr;
                bf[ni][0] = __float_as_uint(cB[kr * SB_STRIDE + nc]);
                bf[ni][1] = __float_as_uint(cB[(kr + 4) * SB_STRIDE + nc]);
            }
            #pragma unroll
            for (int mi = 0; mi < 2; mi++)
                #pragma unroll
                for (int ni = 0; ni < 8; ni++)
                    mma_tf32(acc[mi][ni], af[mi], bf[ni]);
        }
        __syncthreads();
    }

    // ---- epilogue ----
    const float* dq2 = (MODE == 1) ? dq2_all + n * BB : nullptr;
    const float* dk2 = (MODE == 1) ? dk2_all + n * BB : nullptr;

    #pragma unroll
    for (int mi = 0; mi < 2; mi++) {
        const int m = row0 + wm * 32 + mi * 16 + lr;
        float b0 = 0.f, b1 = 0.f, dq0 = 0.f, dq1 = 0.f;
        if (MODE == 0) { b0 = bias[m]; b1 = bias[m + 8]; }
        if (MODE == 1) { dq0 = dq2[m]; dq1 = dq2[m + 8]; }

        #pragma unroll
        for (int ni = 0; ni < 8; ni++) {
            const int nn = col0 + wn * 64 + ni * 8 + 2 * lc;
            float v00 = acc[mi][ni][0], v01 = acc[mi][ni][1];
            float v10 = acc[mi][ni][2], v11 = acc[mi][ni][3];
            if (MODE == 0) {
                v00 = roundtf(v00 + b0); v01 = roundtf(v01 + b0);
                v10 = roundtf(v10 + b1); v11 = roundtf(v11 + b1);
            } else if (MODE == 1) {
                float dk0 = dk2[nn], dk1 = dk2[nn + 1];
                v00 *= rsqrtf(fmaxf(dq0 * dk0, EPS));
                v01 *= rsqrtf(fmaxf(dq0 * dk1, EPS));
                v10 *= rsqrtf(fmaxf(dq1 * dk0, EPS));
                v11 *= rsqrtf(fmaxf(dq1 * dk1, EPS));
            }
            *reinterpret_cast<float2*>(&Cn[(size_t)m * ldc + nn]) = make_float2(v00, v01);
            *reinterpret_cast<float2*>(&Cn[(size_t)(m + 8) * ldc + nn]) = make_float2(v10, v11);
        }
    }
}

// ---------------------------------------------------------------------------
__global__ __launch_bounds__(256)
void tf32_round_kernel(const float* __restrict__ in, float* __restrict__ out, int n4)
{
    int i = blockIdx.x * 256 + threadIdx.x;
    int stride = gridDim.x * 256;
    for (; i < n4; i += stride) {
        float4 v = reinterpret_cast<const float4*>(in)[i];
        v.x = roundtf(v.x); v.y = roundtf(v.y);
        v.z = roundtf(v.z); v.w = roundtf(v.w);
        reinterpret_cast<float4*>(out)[i] = v;
    }
}

// ---------------------------------------------------------------------------
// Column squared norms of K and Q
// ---------------------------------------------------------------------------
__global__ __launch_bounds__(256)
void sq_kernel()
{
    int idx = blockIdx.x * 256 + threadIdx.x;
    int n = idx / BB;
    int b = idx % BB;
    const float* Kn = g_K + (size_t)n * CC * BB + b;
    const float* Qn = g_Q + (size_t)n * CC * BB + b;
    float sk = 0.f, sq = 0.f;
    #pragma unroll 8
    for (int c = 0; c < CC; c++) {
        float kv = Kn[(size_t)c * BB];
        float qv = Qn[(size_t)c * BB];
        sk = fmaf(kv, kv, sk);
        sq = fmaf(qv, qv, sq);
    }
    g_DK2[idx] = sk;
    g_DQ2[idx] = sq;
}

// ---------------------------------------------------------------------------
// Softmax over b (axis=1), in place. Pass 1: online max+sum (single read).
// Pass 2: scale + tf32-round (read+write). 3 sweeps total instead of 5.
// ---------------------------------------------------------------------------
__global__ __launch_bounds__(256)
void softmax_kernel()
{
    const int n = blockIdx.y;
    const int k = blockIdx.x * 256 + threadIdx.x;
    float* Yn = g_Y + (size_t)n * BB * BB + k;

    float m = -INFINITY, s = 0.f;
    #pragma unroll 4
    for (int b = 0; b < BB; b++) {
        float v = Yn[(size_t)b * BB];
        float mn = fmaxf(m, v);
        s = s * expf(m - mn) + expf(v - mn);
        m = mn;
    }

    float inv = 1.f / s;
    #pragma unroll 4
    for (int b = 0; b < BB; b++) {
        float v = Yn[(size_t)b * BB];
        Yn[(size_t)b * BB] = roundtf(expf(v - m) * inv);
    }
}

// ---------------------------------------------------------------------------
extern "C" void kernel_launch(void* const* d_in, const int* in_sizes, int n_in,
                              void* d_out, int out_size)
{
    const float* X    = (const float*)d_in[0];
    const float* Wk_w = (const float*)d_in[1];
    const float* Wk_b = (const float*)d_in[2];
    const float* Wq_w = (const float*)d_in[3];
    const float* Wq_b = (const float*)d_in[4];
    float* Z = (float*)d_out;

    float* Kd;  cudaGetSymbolAddress((void**)&Kd,  g_K);
    float* Qd;  cudaGetSymbolAddress((void**)&Qd,  g_Q);
    float* Yd;  cudaGetSymbolAddress((void**)&Yd,  g_Y);
    float* Xt;  cudaGetSymbolAddress((void**)&Xt,  g_Xt);
    float* Wkt; cudaGetSymbolAddress((void**)&Wkt, g_Wkt);
    float* Wqt; cudaGetSymbolAddress((void**)&Wqt, g_Wqt);
    float* DK2; cudaGetSymbolAddress((void**)&DK2, g_DK2);
    float* DQ2; cudaGetSymbolAddress((void**)&DQ2, g_DQ2);

    const size_t sXn = (size_t)CC * BB;
    const size_t sYn = (size_t)BB * BB;

    constexpr size_t smem_rm = 2 * (size_t)(128 * 20 + SB_SZ) * 4;  // ~54.3 KB
    constexpr size_t smem_km = 2 * (size_t)(16 * 136 + SB_SZ) * 4;  // ~51.2 KB

    static bool attr_done = false;
    if (!attr_done) {
        cudaFuncSetAttribute(gemm_tf32<0, CC, false>,
                             cudaFuncAttributeMaxDynamicSharedMemorySize, (int)smem_rm);
        cudaFuncSetAttribute(gemm_tf32<1, CC, true>,
                             cudaFuncAttributeMaxDynamicSharedMemorySize, (int)smem_km);
        cudaFuncSetAttribute(gemm_tf32<2, BB, false>,
                             cudaFuncAttributeMaxDynamicSharedMemorySize, (int)smem_rm);
        attr_done = true;
    }

    // 0) pre-round operands to tf32
    tf32_round_kernel<<<1024, 256>>>(X, Xt, (int)(NN * sXn / 4));
    tf32_round_kernel<<<256, 256>>>(Wk_w, Wkt, CC * CC / 4);
    tf32_round_kernel<<<256, 256>>>(Wq_w, Wqt, CC * CC / 4);

    // 1) projections (outputs tf32-rounded)
    gemm_tf32<0, CC, false><<<dim3(BB / BN, CC / BM, NN), 512, smem_rm>>>(
        Wkt, CC, 0, Xt, BB, sXn, Kd, BB, sXn, Wk_b, nullptr, nullptr);
    gemm_tf32<0, CC, false><<<dim3(BB / BN, CC / BM, NN), 512, smem_rm>>>(
        Wqt, CC, 0, Xt, BB, sXn, Qd, BB, sXn, Wq_b, nullptr, nullptr);

    // 2) squared norms
    sq_kernel<<<(NN * BB) / 256, 256>>>();

    // 3) normalized scores
    gemm_tf32<1, CC, true><<<dim3(BB / BN, BB / BM, NN), 512, smem_km>>>(
        Qd, BB, sXn, Kd, BB, sXn, Yd, BB, sYn, nullptr, DQ2, DK2);

    // 4) softmax over query axis (in place; output tf32-rounded)
    softmax_kernel<<<dim3(BB / 256, NN), 256>>>();

    // 5) output mix: Z = X @ SM
    gemm_tf32<2, BB, false><<<dim3(BB / BN, CC / BM, NN), 512, smem_rm>>>(
        Xt, BB, sXn, Yd, BB, sYn, Z, BB, sXn, nullptr, nullptr, nullptr);
}

// round 6
// speedup vs baseline: 2.6054x; 2.6054x over previous
#include <cuda_runtime.h>
#include <cuda_fp16.h>
#include <math.h>
#include <stdint.h>

#define NN 8
#define CC 1024
#define BB 2048
#define EPS 1e-12f

// ---- scratch (device globals; no allocation allowed) ----
__device__ __half g_Kh[(size_t)NN * CC * BB];   // K [o][b] fp16
__device__ __half g_Qh[(size_t)NN * CC * BB];   // Q [o][b] fp16
__device__ __half g_Y [(size_t)NN * BB * BB];   // Y [b][k'] fp16, then SM in place
__device__ __half g_Xh[(size_t)NN * CC * BB];   // X fp16 [c][b]
__device__ __half g_Wkh[CC * CC];
__device__ __half g_Wqh[CC * CC];
__device__ float  g_DK2[NN * BB];
__device__ float  g_DQ2[NN * BB];

// ---------------------------------------------------------------------------
__device__ __forceinline__ void cp16s(uint32_t s, const __half* g) {
    asm volatile("cp.async.cg.shared.global [%0], [%1], 16;" :: "r"(s), "l"(g));
}
#define CP_COMMIT() asm volatile("cp.async.commit_group;")

__device__ __forceinline__ void ldm4(uint32_t (&r)[4], uint32_t a) {
    asm volatile("ldmatrix.sync.aligned.m8n8.x4.shared.b16 {%0,%1,%2,%3}, [%4];"
                 : "=r"(r[0]), "=r"(r[1]), "=r"(r[2]), "=r"(r[3]) : "r"(a));
}
__device__ __forceinline__ void ldm4t(uint32_t (&r)[4], uint32_t a) {
    asm volatile("ldmatrix.sync.aligned.m8n8.x4.trans.shared.b16 {%0,%1,%2,%3}, [%4];"
                 : "=r"(r[0]), "=r"(r[1]), "=r"(r[2]), "=r"(r[3]) : "r"(a));
}
__device__ __forceinline__ void mma16(float (&d)[4], const uint32_t (&a)[4],
                                      const uint32_t (&b)[2]) {
    asm volatile(
        "mma.sync.aligned.m16n8k16.row.col.f32.f16.f16.f32 "
        "{%0,%1,%2,%3}, {%4,%5,%6,%7}, {%8,%9}, {%0,%1,%2,%3};"
        : "+f"(d[0]), "+f"(d[1]), "+f"(d[2]), "+f"(d[3])
        : "r"(a[0]), "r"(a[1]), "r"(a[2]), "r"(a[3]), "r"(b[0]), "r"(b[1]));
}

// ===========================================================================
// FP16 warp-MMA GEMM: CTA 128x128, 8 warps (4m x 2n), warp tile 32x64,
// BK=32, 2-stage cp.async, ldmatrix fragment loads.
// D[m][n] = sum_k A[m][k] * B[k][n]
//   A: row-major [m][k] (AKM=false) or k-major [k][m] (AKM=true) in gmem.
//   B: [k][n] n-contiguous in gmem.
// MODE 0: proj  (out half: acc + bias[m])
// MODE 1: score (out half: acc * rsqrt(max(dq2[m]*dk2[n], EPS)))
// MODE 2: mix   (out float: acc)
// ===========================================================================
#define BK 32
#define ARM_STR 40     // A row-major smem stride (halves): 32 + 8 pad
#define KM_STR 136     // k-major smem stride (halves): 128 + 8 pad

template <int MODE, int KDIM, bool AKM, typename OutT>
__global__ __launch_bounds__(256)
void gemm_h(const __half* __restrict__ A, int lda, size_t strA,
            const __half* __restrict__ B, int ldb, size_t strB,
            OutT* __restrict__ C, int ldc, size_t strC,
            const float* __restrict__ bias,
            const float* __restrict__ dq2_all,
            const float* __restrict__ dk2_all)
{
    constexpr int SA = AKM ? BK * KM_STR : 128 * ARM_STR;
    constexpr int SB = BK * KM_STR;
    __shared__ __half sA[2][SA];
    __shared__ __half sB[2][SB];
    __shared__ float s_dk[128];

    const int nb = blockIdx.z;
    const __half* An = A + (size_t)nb * strA;
    const __half* Bn = B + (size_t)nb * strB;
    OutT* Cn = C + (size_t)nb * strC;
    const int row0 = blockIdx.y * 128;
    const int col0 = blockIdx.x * 128;

    const int tid = threadIdx.x;
    const int lane = tid & 31;
    const int wid = tid >> 5;
    const int wm = wid >> 1;    // 0..3 (32-row slab)
    const int wn = wid & 1;     // 0..1 (64-col slab)
    const int l7 = lane & 7;
    const int g = lane >> 3;

    if (MODE == 1 && tid < 128)
        s_dk[tid] = dk2_all[(size_t)nb * BB + col0 + tid];

    float acc[2][8][4] = {};

    auto ldA = [&](int st, int kt) {
        uint32_t sb = (uint32_t)__cvta_generic_to_shared(&sA[st][0]);
        if (!AKM) {
            #pragma unroll
            for (int i = tid; i < 512; i += 256) {       // 128 rows x 4 chunks
                int m = i >> 2, c = i & 3;
                cp16s(sb + (m * ARM_STR + c * 8) * 2,
                      An + (size_t)(row0 + m) * lda + kt * BK + c * 8);
            }
        } else {
            #pragma unroll
            for (int i = tid; i < 512; i += 256) {       // 32 rows x 16 chunks
                int k = i >> 4, c = i & 15;
                cp16s(sb + (k * KM_STR + c * 8) * 2,
                      An + (size_t)(kt * BK + k) * lda + row0 + c * 8);
            }
        }
    };
    auto ldB = [&](int st, int kt) {
        uint32_t sb = (uint32_t)__cvta_generic_to_shared(&sB[st][0]);
        #pragma unroll
        for (int i = tid; i < 512; i += 256) {
            int k = i >> 4, c = i & 15;
            cp16s(sb + (k * KM_STR + c * 8) * 2,
                  Bn + (size_t)(kt * BK + k) * ldb + col0 + c * 8);
        }
    };

    constexpr int KT = KDIM / BK;

    ldA(0, 0); ldB(0, 0); CP_COMMIT();

    for (int kt = 0; kt < KT; kt++) {
        const int buf = kt & 1;
        if (kt + 1 < KT) {
            ldA(buf ^ 1, kt + 1);
            ldB(buf ^ 1, kt + 1);
            CP_COMMIT();
            asm volatile("cp.async.wait_group 1;");
        } else {
            asm volatile("cp.async.wait_group 0;");
        }
        __syncthreads();

        uint32_t aA = (uint32_t)__cvta_generic_to_shared(&sA[buf][0]);
        uint32_t aB = (uint32_t)__cvta_generic_to_shared(&sB[buf][0]);

        #pragma unroll
        for (int ks = 0; ks < 2; ks++) {
            uint32_t af[2][4];
            uint32_t bf[8][2];

            // A fragments (m32 x k16): 2 x ldmatrix.x4
            #pragma unroll
            for (int mi = 0; mi < 2; mi++) {
                uint32_t addr;
                if (!AKM) {
                    int m = wm * 32 + mi * 16 + l7 + (g & 1) * 8;
                    int k = ks * 16 + (g >> 1) * 8;
                    addr = aA + (m * ARM_STR + k) * 2;
                    ldm4(af[mi], addr);
                } else {
                    int k = ks * 16 + (g >> 1) * 8 + l7;
                    int m = wm * 32 + mi * 16 + (g & 1) * 8;
                    addr = aA + (k * KM_STR + m) * 2;
                    ldm4t(af[mi], addr);
                }
            }
            // B fragments (k16 x n64): 4 x ldmatrix.x4.trans, each covers 2 n8 tiles
            #pragma unroll
            for (int j = 0; j < 4; j++) {
                int k = ks * 16 + (g & 1) * 8 + l7;
                int nn = wn * 64 + j * 16 + (g >> 1) * 8;
                uint32_t r[4];
                ldm4t(r, aB + (k * KM_STR + nn) * 2);
                bf[2 * j][0] = r[0];  bf[2 * j][1] = r[1];
                bf[2 * j + 1][0] = r[2];  bf[2 * j + 1][1] = r[3];
            }
            #pragma unroll
            for (int mi = 0; mi < 2; mi++)
                #pragma unroll
                for (int ni = 0; ni < 8; ni++)
                    mma16(acc[mi][ni], af[mi], bf[ni]);
        }
        __syncthreads();
    }

    // ---- epilogue ----
    const int lr = lane >> 2, lc = lane & 3;
    const float* dq2 = (MODE == 1) ? dq2_all + (size_t)nb * BB : nullptr;

    #pragma unroll
    for (int mi = 0; mi < 2; mi++) {
        const int m = row0 + wm * 32 + mi * 16 + lr;
        float b0 = 0.f, b1 = 0.f, dqa = 0.f, dqb = 0.f;
        if (MODE == 0) { b0 = bias[m]; b1 = bias[m + 8]; }
        if (MODE == 1) { dqa = dq2[m]; dqb = dq2[m + 8]; }

        #pragma unroll
        for (int ni = 0; ni < 8; ni++) {
            const int cl = wn * 64 + ni * 8 + 2 * lc;   // local col in [0,128)
            const int nn = col0 + cl;
            float v0 = acc[mi][ni][0], v1 = acc[mi][ni][1];
            float v2 = acc[mi][ni][2], v3 = acc[mi][ni][3];
            if (MODE == 0) {
                v0 += b0; v1 += b0; v2 += b1; v3 += b1;
            } else if (MODE == 1) {
                float dk0 = s_dk[cl], dk1 = s_dk[cl + 1];
                v0 *= rsqrtf(fmaxf(dqa * dk0, EPS));
                v1 *= rsqrtf(fmaxf(dqa * dk1, EPS));
                v2 *= rsqrtf(fmaxf(dqb * dk0, EPS));
                v3 *= rsqrtf(fmaxf(dqb * dk1, EPS));
            }
            if (MODE == 2) {
                float* p0 = (float*)&Cn[(size_t)m * ldc + nn];
                float* p1 = (float*)&Cn[(size_t)(m + 8) * ldc + nn];
                *reinterpret_cast<float2*>(p0) = make_float2(v0, v1);
                *reinterpret_cast<float2*>(p1) = make_float2(v2, v3);
            } else {
                __half* p0 = (__half*)&Cn[(size_t)m * ldc + nn];
                __half* p1 = (__half*)&Cn[(size_t)(m + 8) * ldc + nn];
                *reinterpret_cast<__half2*>(p0) = __floats2half2_rn(v0, v1);
                *reinterpret_cast<__half2*>(p1) = __floats2half2_rn(v2, v3);
            }
        }
    }
}

// ---------------------------------------------------------------------------
__global__ __launch_bounds__(256)
void to_half_kernel(const float* __restrict__ in, __half* __restrict__ out, int n4)
{
    int i = blockIdx.x * 256 + threadIdx.x;
    int stride = gridDim.x * 256;
    for (; i < n4; i += stride) {
        float4 v = reinterpret_cast<const float4*>(in)[i];
        __half2* o = reinterpret_cast<__half2*>(out) + 2 * i;
        o[0] = __floats2half2_rn(v.x, v.y);
        o[1] = __floats2half2_rn(v.z, v.w);
    }
}

// ---------------------------------------------------------------------------
// Column squared norms of K and Q (fp16 in, fp32 sums)
// ---------------------------------------------------------------------------
__global__ __launch_bounds__(256)
void sq_kernel()
{
    int idx = blockIdx.x * 256 + threadIdx.x;      // over NN * BB/2
    int n = idx / (BB / 2);
    int b2 = idx % (BB / 2);
    const __half2* Kn = (const __half2*)(g_Kh + (size_t)n * CC * BB) + b2;
    const __half2* Qn = (const __half2*)(g_Qh + (size_t)n * CC * BB) + b2;
    float skx = 0.f, sky = 0.f, sqx = 0.f, sqy = 0.f;
    #pragma unroll 8
    for (int c = 0; c < CC; c++) {
        float2 k2 = __half22float2(Kn[(size_t)c * (BB / 2)]);
        float2 q2 = __half22float2(Qn[(size_t)c * (BB / 2)]);
        skx = fmaf(k2.x, k2.x, skx); sky = fmaf(k2.y, k2.y, sky);
        sqx = fmaf(q2.x, q2.x, sqx); sqy = fmaf(q2.y, q2.y, sqy);
    }
    g_DK2[n * BB + 2 * b2] = skx;  g_DK2[n * BB + 2 * b2 + 1] = sky;
    g_DQ2[n * BB + 2 * b2] = sqx;  g_DQ2[n * BB + 2 * b2 + 1] = sqy;
}

// ---------------------------------------------------------------------------
// exp(x) for x in [-1.05, 1.05] via Taylor to x^9 (rel err ~3e-7) — pure FMA,
// avoids the MUFU throughput wall. Valid because cosine scores are bounded.
// ---------------------------------------------------------------------------
__device__ __forceinline__ float exp_poly(float x)
{
    float r = fmaf(x, 1.f / 9.f, 1.f);
    r = fmaf(r * x, 1.f / 8.f, 1.f);
    r = fmaf(r * x, 1.f / 7.f, 1.f);
    r = fmaf(r * x, 1.f / 6.f, 1.f);
    r = fmaf(r * x, 1.f / 5.f, 1.f);
    r = fmaf(r * x, 1.f / 4.f, 1.f);
    r = fmaf(r * x, 1.f / 3.f, 1.f);
    r = fmaf(r * x, 0.5f, 1.f);
    return fmaf(r, x, 1.f);
}

// ---------------------------------------------------------------------------
// Softmax over b (axis=1) of Y[n][b][k'], in place, fp16. No max-shift needed
// (|Y| <= ~1). Each thread: 2 adjacent k' columns via half2.
// ---------------------------------------------------------------------------
__global__ __launch_bounds__(256)
void softmax_kernel()
{
    const int n = blockIdx.y;
    const int k2 = blockIdx.x * 256 + threadIdx.x;   // over BB/2
    __half2* Yn = (__half2*)(g_Y + (size_t)n * BB * BB) + k2;

    float sx = 0.f, sy = 0.f;
    #pragma unroll 4
    for (int b = 0; b < BB; b++) {
        float2 v = __half22float2(Yn[(size_t)b * (BB / 2)]);
        sx += exp_poly(v.x);
        sy += exp_poly(v.y);
    }
    const float ix = 1.f / sx, iy = 1.f / sy;
    #pragma unroll 4
    for (int b = 0; b < BB; b++) {
        float2 v = __half22float2(Yn[(size_t)b * (BB / 2)]);
        Yn[(size_t)b * (BB / 2)] =
            __floats2half2_rn(exp_poly(v.x) * ix, exp_poly(v.y) * iy);
    }
}

// ---------------------------------------------------------------------------
extern "C" void kernel_launch(void* const* d_in, const int* in_sizes, int n_in,
                              void* d_out, int out_size)
{
    const float* X    = (const float*)d_in[0];
    const float* Wk_w = (const float*)d_in[1];
    const float* Wk_b = (const float*)d_in[2];
    const float* Wq_w = (const float*)d_in[3];
    const float* Wq_b = (const float*)d_in[4];
    float* Z = (float*)d_out;

    __half* Kh;  cudaGetSymbolAddress((void**)&Kh,  g_Kh);
    __half* Qh;  cudaGetSymbolAddress((void**)&Qh,  g_Qh);
    __half* Yd;  cudaGetSymbolAddress((void**)&Yd,  g_Y);
    __half* Xh;  cudaGetSymbolAddress((void**)&Xh,  g_Xh);
    __half* Wkh; cudaGetSymbolAddress((void**)&Wkh, g_Wkh);
    __half* Wqh; cudaGetSymbolAddress((void**)&Wqh, g_Wqh);
    float* DK2;  cudaGetSymbolAddress((void**)&DK2, g_DK2);
    float* DQ2;  cudaGetSymbolAddress((void**)&DQ2, g_DQ2);

    const size_t sXn = (size_t)CC * BB;   // per-n elems of X/K/Q
    const size_t sYn = (size_t)BB * BB;

    // 0) convert operands to fp16
    to_half_kernel<<<2048, 256>>>(X, Xh, (int)(NN * sXn / 4));
    to_half_kernel<<<256, 256>>>(Wk_w, Wkh, CC * CC / 4);
    to_half_kernel<<<256, 256>>>(Wq_w, Wqh, CC * CC / 4);

    // 1) projections: K/Q[o][b] = W[o][c] @ X[c][b] + bias  (A rm, B [k][n])
    gemm_h<0, CC, false, __half><<<dim3(BB / 128, CC / 128, NN), 256>>>(
        Wkh, CC, 0, Xh, BB, sXn, Kh, BB, sXn, Wk_b, nullptr, nullptr);
    gemm_h<0, CC, false, __half><<<dim3(BB / 128, CC / 128, NN), 256>>>(
        Wqh, CC, 0, Xh, BB, sXn, Qh, BB, sXn, Wq_b, nullptr, nullptr);

    // 2) squared norms
    sq_kernel<<<(NN * BB / 2) / 256, 256>>>();

    // 3) scores: Y[b][k'] = sum_c Q[c][b] K[c][k'] * rsqrt(dq2[b] dk2[k'])
    //    A = Q k-major ([c][b], k=c), B = K [c][k']
    gemm_h<1, CC, true, __half><<<dim3(BB / 128, BB / 128, NN), 256>>>(
        Qh, BB, sXn, Kh, BB, sXn, Yd, BB, sYn, nullptr, DQ2, DK2);

    // 4) softmax over b (query axis), in place
    softmax_kernel<<<dim3(BB / 512, NN), 256>>>();

    // 5) mix: Z[c][k'] = sum_b X[c][b] SM[b][k']  (A rm = X, B = SM [b][k'])
    gemm_h<2, BB, false, float><<<dim3(BB / 128, CC / 128, NN), 256>>>(
        Xh, BB, sXn, Yd, BB, sYn, Z, BB, sXn, nullptr, nullptr, nullptr);
}